// round 7
// baseline (speedup 1.0000x reference)
#include <cuda_runtime.h>

namespace {
constexpr int   Bb     = 256;
constexpr int   Nn     = 128;
constexpr int   Mm     = 192;
constexpr int   PA     = 129;   // smem pitch (odd -> conflict-free rows AND columns)
constexpr int   PH     = 129;
constexpr float RHO    = 0.1f;
constexpr float SIGMA  = 1e-6f;
constexpr float ALPHA  = 1.6f;
constexpr int   NITERS = 400;
constexpr int   NT     = 256;
constexpr int   PPART  = 144;   // partial-matrix pitch: 144 % 32 == 16 -> the two
                                // ty-halves of a warp hit disjoint bank groups

// shared memory layout (floats)
constexpr int OFF_A    = 0;                   // A pitched (dead after reg load;
                                              // reused as the P1 partial matrix)
constexpr int OFF_H    = OFF_A + Mm * PA;     // H then H^{-1}
constexpr int OFF_Q    = OFF_H + Nn * PH;
constexpr int OFF_L    = OFF_Q + Nn;
constexpr int OFF_U    = OFF_L + Mm;
constexpr int OFF_X    = OFF_U + Mm;
constexpr int OFF_W    = OFF_X + Nn;
constexpr int OFF_RHS  = OFF_W + Mm;
constexpr int OFF_XT   = OFF_RHS + Nn;
constexpr int OFF_SNAP = OFF_XT + Nn;         // 256 floats: GJ row/col snapshots
constexpr int SMEM_FLOATS = OFF_SNAP + 256;
static_assert(16 * PPART <= Mm * PA, "partial matrix must fit in dead A region");
static_assert(SMEM_FLOATS * 4 <= 227 * 1024, "");
}

extern __shared__ float smem[];

__global__ __launch_bounds__(NT, 1)
void osqp_admm_kernel(const float* __restrict__ gP,
                      const float* __restrict__ gq,
                      const float* __restrict__ gA,
                      const float* __restrict__ gl,
                      const float* __restrict__ gu,
                      float* __restrict__ gout)
{
    const int b   = blockIdx.x;
    const int tid = threadIdx.x;
    const int ty  = tid >> 4;        // 0..15
    const int tx  = tid & 15;        // 0..15
    const bool lead = (tx == 0);     // one leader per 16-lane half-warp

    float* sA    = smem + OFF_A;
    float* sH    = smem + OFF_H;
    float* sq    = smem + OFF_Q;
    float* sl    = smem + OFF_L;
    float* su    = smem + OFF_U;
    float* sx    = smem + OFF_X;
    float* sw    = smem + OFF_W;
    float* srhs  = smem + OFF_RHS;
    float* sxt   = smem + OFF_XT;
    float* snap  = smem + OFF_SNAP;
    float* spart = smem + OFF_A;     // P1 partials (16 x PPART), aliases dead A

    // ------------------------------------------------------------------
    // Phase 0: load A (pitched), H = P + sigma*I, vectors; init state
    // ------------------------------------------------------------------
    {
        const float* pA = gA + (size_t)b * Mm * Nn;
        for (int idx = tid; idx < Mm * Nn; idx += NT)
            sA[(idx >> 7) * PA + (idx & 127)] = pA[idx];

        const float* pP = gP + (size_t)b * Nn * Nn;
        for (int idx = tid; idx < Nn * Nn; idx += NT) {
            int i = idx >> 7, j = idx & 127;
            float v = pP[idx];
            if (i == j) v += SIGMA;
            sH[i * PH + j] = v;
        }
        for (int n = tid; n < Nn; n += NT) { sq[n] = gq[(size_t)b * Nn + n]; sx[n] = 0.f; }
        for (int m = tid; m < Mm; m += NT) {
            sl[m] = gl[(size_t)b * Mm + m];
            su[m] = gu[(size_t)b * Mm + m];
            sw[m] = 0.f;
        }
    }
    __syncthreads();

    // ------------------------------------------------------------------
    // Phase 1: H += rho * A^T A    (8x8 register tile per thread)
    // ------------------------------------------------------------------
    {
        const int i0 = ty * 8;
        float acc[8][8];
        #pragma unroll
        for (int r = 0; r < 8; r++)
            #pragma unroll
            for (int c = 0; c < 8; c++) acc[r][c] = 0.f;

        #pragma unroll 2
        for (int m = 0; m < Mm; m++) {
            const float* row = sA + m * PA;
            float av[8], bv[8];
            #pragma unroll
            for (int r = 0; r < 8; r++) av[r] = row[i0 + r];
            #pragma unroll
            for (int c = 0; c < 8; c++) bv[c] = row[tx + 16 * c];
            #pragma unroll
            for (int r = 0; r < 8; r++)
                #pragma unroll
                for (int c = 0; c < 8; c++)
                    acc[r][c] += av[r] * bv[c];
        }
        #pragma unroll
        for (int r = 0; r < 8; r++)
            #pragma unroll
            for (int c = 0; c < 8; c++)
                sH[(i0 + r) * PH + tx + 16 * c] += RHO * acc[r][c];
    }
    __syncthreads();

    // ------------------------------------------------------------------
    // Phase 2: in-place Gauss-Jordan inverse of H (SPD -> no pivoting)
    // ------------------------------------------------------------------
    {
        float* srk = snap;         // row-k snapshot (128)
        float* sck = snap + Nn;    // col-k snapshot (128)
        for (int k = 0; k < Nn; k++) {
            const float p = 1.0f / sH[k * PH + k];
            if (tid < Nn) srk[tid] = sH[k * PH + tid];
            else          sck[tid - Nn] = sH[(tid - Nn) * PH + k];
            __syncthreads();

            const int  j   = tid & 127;
            const int  i0  = (tid >> 7) * 64;
            const float rs = srk[j] * p;
            const bool jk  = (j == k);
            #pragma unroll 4
            for (int i = i0; i < i0 + 64; i++) {
                float hij = sH[i * PH + j];
                float f   = sck[i];
                float nv;
                if (i == k) nv = jk ? p : rs;
                else        nv = jk ? (-f * p) : fmaf(-f, rs, hij);
                sH[i * PH + j] = nv;
            }
            __syncthreads();
        }
    }
    // sH now holds M1 = H^{-1} (symmetric up to rounding)

    // ------------------------------------------------------------------
    // Phase 2b: load A and M1 into registers.
    //   rA[k][j] = A[ty+16k][tx+16j]   (12 x 8 per thread)
    //   rM[k][j] = M1[ty+16k][tx+16j]  ( 8 x 8 per thread)
    // z,y live in leader registers (leader ty owns rows m = ty+16k).
    // ------------------------------------------------------------------
    float rA[12][8];
    #pragma unroll
    for (int k = 0; k < 12; k++)
        #pragma unroll
        for (int j = 0; j < 8; j++)
            rA[k][j] = sA[(ty + 16 * k) * PA + (tx + 16 * j)];

    float rM[8][8];
    #pragma unroll
    for (int k = 0; k < 8; k++)
        #pragma unroll
        for (int j = 0; j < 8; j++)
            rM[k][j] = sH[(ty + 16 * k) * PH + (tx + 16 * j)];

    float rz[12], ry[12];
    #pragma unroll
    for (int k = 0; k < 12; k++) { rz[k] = 0.f; ry[k] = 0.f; }

    __syncthreads();   // everyone done reading sA before spart aliases it

    // ------------------------------------------------------------------
    // Phase 3: 400 ADMM iterations; matrices in registers.
    //   rhs = sigma*x - q + A^T w      (reduce over ty -> smem partials)
    //   xt  = M1 * rhs                 (reduce over tx -> shfl)
    //   x   = alpha*xt + (1-alpha)*x
    //   zt  = A*xt                     (reduce over tx -> shfl)
    //   zc  = alpha*zt+(1-alpha)*z
    //   z   = clip(zc + y/rho, l, u); y += rho*(zc - z); w = rho*z - y
    // ------------------------------------------------------------------
    for (int it = 0; it < NITERS; it++) {
        // ---- P1: partial A^T w over this thread's 12 m-rows ----
        {
            float p[8];
            #pragma unroll
            for (int j = 0; j < 8; j++) p[j] = 0.f;
            #pragma unroll
            for (int k = 0; k < 12; k++) {
                const float wk = sw[ty + 16 * k];
                #pragma unroll
                for (int j = 0; j < 8; j++)
                    p[j] = fmaf(rA[k][j], wk, p[j]);
            }
            #pragma unroll
            for (int j = 0; j < 8; j++)
                spart[ty * PPART + tx + 16 * j] = p[j];
        }
        __syncthreads();

        // ---- P2: combine rhs (128 threads, one column each) ----
        if (tid < Nn) {
            float s0 = 0.f, s1 = 0.f;
            #pragma unroll
            for (int t = 0; t < 16; t += 2) {
                s0 += spart[t * PPART + tid];
                s1 += spart[(t + 1) * PPART + tid];
            }
            srhs[tid] = fmaf(SIGMA, sx[tid], (s0 + s1) - sq[tid]);
        }
        __syncthreads();

        // ---- P3: xt = M1 * rhs (shfl-reduce over tx) ----
        {
            float t8[8];
            #pragma unroll
            for (int k = 0; k < 8; k++) t8[k] = 0.f;
            #pragma unroll
            for (int j = 0; j < 8; j++) {
                const float rj = srhs[tx + 16 * j];
                #pragma unroll
                for (int k = 0; k < 8; k++)
                    t8[k] = fmaf(rM[k][j], rj, t8[k]);
            }
            #pragma unroll
            for (int s = 8; s >= 1; s >>= 1)
                #pragma unroll
                for (int k = 0; k < 8; k++)
                    t8[k] += __shfl_xor_sync(0xffffffffu, t8[k], s, 16);
            if (lead) {
                #pragma unroll
                for (int k = 0; k < 8; k++) {
                    const int i = ty + 16 * k;
                    sxt[i] = t8[k];
                    sx[i]  = fmaf(ALPHA, t8[k], (1.0f - ALPHA) * sx[i]);
                }
            }
        }
        __syncthreads();

        // ---- P5: zt = A*xt (shfl-reduce) fused with z/y/w update ----
        {
            float p12[12];
            #pragma unroll
            for (int k = 0; k < 12; k++) p12[k] = 0.f;
            #pragma unroll
            for (int j = 0; j < 8; j++) {
                const float xj = sxt[tx + 16 * j];
                #pragma unroll
                for (int k = 0; k < 12; k++)
                    p12[k] = fmaf(rA[k][j], xj, p12[k]);
            }
            #pragma unroll
            for (int s = 8; s >= 1; s >>= 1)
                #pragma unroll
                for (int k = 0; k < 12; k++)
                    p12[k] += __shfl_xor_sync(0xffffffffu, p12[k], s, 16);
            if (lead) {
                #pragma unroll
                for (int k = 0; k < 12; k++) {
                    const int m  = ty + 16 * k;
                    const float zc = fmaf(ALPHA, p12[k], (1.0f - ALPHA) * rz[k]);
                    const float yv = ry[k];
                    const float v  = fmaf(yv, 1.0f / RHO, zc);
                    const float zn = fminf(fmaxf(v, sl[m]), su[m]);
                    const float yn = fmaf(RHO, zc - zn, yv);
                    rz[k] = zn;
                    ry[k] = yn;
                    sw[m] = fmaf(RHO, zn, -yn);
                }
            }
        }
        __syncthreads();
    }

    // ------------------------------------------------------------------
    // Output
    // ------------------------------------------------------------------
    for (int n = tid; n < Nn; n += NT)
        gout[(size_t)b * Nn + n] = sx[n];
}

extern "C" void kernel_launch(void* const* d_in, const int* in_sizes, int n_in,
                              void* d_out, int out_size)
{
    const float* P = (const float*)d_in[0];   // (256,128,128)
    const float* q = (const float*)d_in[1];   // (256,128)
    const float* A = (const float*)d_in[2];   // (256,192,128)
    const float* l = (const float*)d_in[3];   // (256,192)
    const float* u = (const float*)d_in[4];   // (256,192)
    float* out = (float*)d_out;               // (256,128)

    const int smem_bytes = SMEM_FLOATS * (int)sizeof(float);
    // Unconditional (no static guard). Not stream-ordered -> capture-legal; idempotent.
    cudaFuncSetAttribute(osqp_admm_kernel,
                         cudaFuncAttributeMaxDynamicSharedMemorySize,
                         smem_bytes);
    osqp_admm_kernel<<<Bb, NT, smem_bytes>>>(P, q, A, l, u, out);
}

// round 8
// speedup vs baseline: 1.7279x; 1.7279x over previous
#include <cuda_runtime.h>

namespace {
constexpr int   Bb     = 256;
constexpr int   Nn     = 128;
constexpr int   Mm     = 192;
constexpr int   PA     = 129;   // smem pitch (odd -> conflict-free rows AND columns)
constexpr int   PH     = 129;
constexpr float RHO    = 0.1f;
constexpr float SIGMA  = 1e-6f;
constexpr float ALPHA  = 1.6f;
constexpr int   NITERS = 400;
constexpr int   NT     = 512;   // 16 warps -> 4 per SMSP
constexpr int   PPART  = 144;   // partial pitch (144%32==16 -> warp halves disjoint)

// shared memory layout (floats)
constexpr int OFF_A    = 0;                   // A pitched (dead after reg load;
                                              // start reused as P1 partials 32xPPART)
constexpr int OFF_H    = OFF_A + Mm * PA;     // H then H^{-1}
constexpr int OFF_Q    = OFF_H + Nn * PH;
constexpr int OFF_L    = OFF_Q + Nn;
constexpr int OFF_U    = OFF_L + Mm;
constexpr int OFF_X    = OFF_U + Mm;
constexpr int OFF_Z    = OFF_X + Nn;
constexpr int OFF_Y    = OFF_Z + Mm;
constexpr int OFF_W    = OFF_Y + Mm;
constexpr int OFF_RHS  = OFF_W + Mm;
constexpr int OFF_XT   = OFF_RHS + Nn;
constexpr int OFF_SNAP = OFF_XT + Nn;         // 256 floats: GJ row/col snapshots
constexpr int SMEM_FLOATS = OFF_SNAP + 256;
static_assert(32 * PPART <= Mm * PA, "P1 partials must fit in dead A region");
static_assert(SMEM_FLOATS * 4 <= 227 * 1024, "");
}

extern __shared__ float smem[];

__global__ __launch_bounds__(NT, 1)
void osqp_admm_kernel(const float* __restrict__ gP,
                      const float* __restrict__ gq,
                      const float* __restrict__ gA,
                      const float* __restrict__ gl,
                      const float* __restrict__ gu,
                      float* __restrict__ gout)
{
    const int b   = blockIdx.x;
    const int tid = threadIdx.x;
    const int ty  = tid >> 4;        // 0..31
    const int tx  = tid & 15;        // 0..15
    const bool lead = (tx == 0);     // lanes 0 and 16 of each warp

    float* sA    = smem + OFF_A;
    float* sH    = smem + OFF_H;
    float* sq    = smem + OFF_Q;
    float* sl    = smem + OFF_L;
    float* su    = smem + OFF_U;
    float* sx    = smem + OFF_X;
    float* sz    = smem + OFF_Z;
    float* sy    = smem + OFF_Y;
    float* sw    = smem + OFF_W;
    float* srhs  = smem + OFF_RHS;
    float* sxt   = smem + OFF_XT;
    float* snap  = smem + OFF_SNAP;
    float* spart = smem + OFF_A;     // P1 partials (32 x PPART), aliases dead A

    // ------------------------------------------------------------------
    // Phase 0: load A (pitched), H = P + sigma*I, vectors; init state
    // ------------------------------------------------------------------
    {
        const float* pA = gA + (size_t)b * Mm * Nn;
        for (int idx = tid; idx < Mm * Nn; idx += NT)
            sA[(idx >> 7) * PA + (idx & 127)] = pA[idx];

        const float* pP = gP + (size_t)b * Nn * Nn;
        for (int idx = tid; idx < Nn * Nn; idx += NT) {
            int i = idx >> 7, j = idx & 127;
            float v = pP[idx];
            if (i == j) v += SIGMA;
            sH[i * PH + j] = v;
        }
        for (int n = tid; n < Nn; n += NT) { sq[n] = gq[(size_t)b * Nn + n]; sx[n] = 0.f; }
        for (int m = tid; m < Mm; m += NT) {
            sl[m] = gl[(size_t)b * Mm + m];
            su[m] = gu[(size_t)b * Mm + m];
            sz[m] = 0.f; sy[m] = 0.f; sw[m] = 0.f;
        }
    }
    __syncthreads();

    // ------------------------------------------------------------------
    // Phase 1: H += rho * A^T A   (8x4 register tile, 16x32 thread grid)
    // ------------------------------------------------------------------
    {
        const int ty1 = tid >> 5;    // 0..15
        const int tx1 = tid & 31;    // 0..31
        const int i0  = ty1 * 8;
        float acc[8][4];
        #pragma unroll
        for (int r = 0; r < 8; r++)
            #pragma unroll
            for (int c = 0; c < 4; c++) acc[r][c] = 0.f;

        #pragma unroll 2
        for (int m = 0; m < Mm; m++) {
            const float* row = sA + m * PA;
            float av[8], bv[4];
            #pragma unroll
            for (int r = 0; r < 8; r++) av[r] = row[i0 + r];      // broadcast
            #pragma unroll
            for (int c = 0; c < 4; c++) bv[c] = row[tx1 + 32 * c]; // coalesced
            #pragma unroll
            for (int r = 0; r < 8; r++)
                #pragma unroll
                for (int c = 0; c < 4; c++)
                    acc[r][c] += av[r] * bv[c];
        }
        #pragma unroll
        for (int r = 0; r < 8; r++)
            #pragma unroll
            for (int c = 0; c < 4; c++)
                sH[(i0 + r) * PH + tx1 + 32 * c] += RHO * acc[r][c];
    }
    __syncthreads();

    // ------------------------------------------------------------------
    // Phase 2: in-place Gauss-Jordan inverse of H (SPD -> no pivoting)
    // 512 threads: column j = tid&127, 32 rows per thread.
    // ------------------------------------------------------------------
    {
        float* srk = snap;         // row-k snapshot (128)
        float* sck = snap + Nn;    // col-k snapshot (128)
        for (int k = 0; k < Nn; k++) {
            const float p = 1.0f / sH[k * PH + k];
            if (tid < Nn)            srk[tid] = sH[k * PH + tid];
            else if (tid < 2 * Nn)   sck[tid - Nn] = sH[(tid - Nn) * PH + k];
            __syncthreads();

            const int  j   = tid & 127;
            const int  i0  = (tid >> 7) * 32;
            const float rs = srk[j] * p;
            const bool jk  = (j == k);
            #pragma unroll 4
            for (int i = i0; i < i0 + 32; i++) {
                float hij = sH[i * PH + j];
                float f   = sck[i];
                float nv;
                if (i == k) nv = jk ? p : rs;
                else        nv = jk ? (-f * p) : fmaf(-f, rs, hij);
                sH[i * PH + j] = nv;
            }
            __syncthreads();
        }
    }
    // sH now holds M1 = H^{-1}

    // ------------------------------------------------------------------
    // Phase 2b: load A and M1 into registers.
    //   rA[k][j] = A[ty+32k][tx+16j]   (6 x 8 per thread)
    //   rM[k][j] = M1[ty+32k][tx+16j]  (4 x 8 per thread)
    // ------------------------------------------------------------------
    float rA[6][8];
    #pragma unroll
    for (int k = 0; k < 6; k++)
        #pragma unroll
        for (int j = 0; j < 8; j++)
            rA[k][j] = sA[(ty + 32 * k) * PA + (tx + 16 * j)];

    float rM[4][8];
    #pragma unroll
    for (int k = 0; k < 4; k++)
        #pragma unroll
        for (int j = 0; j < 8; j++)
            rM[k][j] = sH[(ty + 32 * k) * PH + (tx + 16 * j)];

    __syncthreads();   // all sA reads done before spart aliases it

    // ------------------------------------------------------------------
    // Phase 3: 400 ADMM iterations; matrices in registers, 16 warps.
    // ------------------------------------------------------------------
    for (int it = 0; it < NITERS; it++) {
        // ---- P1: partial A^T w over this thread's 6 m-rows ----
        {
            float p[8];
            #pragma unroll
            for (int j = 0; j < 8; j++) p[j] = 0.f;
            #pragma unroll
            for (int k = 0; k < 6; k++) {
                const float wk = sw[ty + 32 * k];
                #pragma unroll
                for (int j = 0; j < 8; j++)
                    p[j] = fmaf(rA[k][j], wk, p[j]);
            }
            #pragma unroll
            for (int j = 0; j < 8; j++)
                spart[ty * PPART + tx + 16 * j] = p[j];
        }
        __syncthreads();

        // ---- P2: combine rhs (threads 0..127, one column each) ----
        if (tid < Nn) {
            float s0 = 0.f, s1 = 0.f, s2 = 0.f, s3 = 0.f;
            #pragma unroll
            for (int t = 0; t < 32; t += 4) {
                s0 += spart[(t + 0) * PPART + tid];
                s1 += spart[(t + 1) * PPART + tid];
                s2 += spart[(t + 2) * PPART + tid];
                s3 += spart[(t + 3) * PPART + tid];
            }
            srhs[tid] = fmaf(SIGMA, sx[tid], ((s0 + s1) + (s2 + s3)) - sq[tid]);
        }
        __syncthreads();

        // ---- P3: xt = M1 * rhs (shfl-reduce over tx) + x update ----
        {
            float t4[4];
            #pragma unroll
            for (int k = 0; k < 4; k++) t4[k] = 0.f;
            #pragma unroll
            for (int j = 0; j < 8; j++) {
                const float rj = srhs[tx + 16 * j];
                #pragma unroll
                for (int k = 0; k < 4; k++)
                    t4[k] = fmaf(rM[k][j], rj, t4[k]);
            }
            #pragma unroll
            for (int s = 8; s >= 1; s >>= 1)
                #pragma unroll
                for (int k = 0; k < 4; k++)
                    t4[k] += __shfl_xor_sync(0xffffffffu, t4[k], s, 16);
            if (lead) {
                #pragma unroll
                for (int k = 0; k < 4; k++) {
                    const int i = ty + 32 * k;
                    sxt[i] = t4[k];
                    sx[i]  = fmaf(ALPHA, t4[k], (1.0f - ALPHA) * sx[i]);
                }
            }
        }
        __syncthreads();

        // ---- P5: zt = A*xt (shfl-reduce) fused with z/y/w update ----
        {
            float p6[6];
            #pragma unroll
            for (int k = 0; k < 6; k++) p6[k] = 0.f;
            #pragma unroll
            for (int j = 0; j < 8; j++) {
                const float xj = sxt[tx + 16 * j];
                #pragma unroll
                for (int k = 0; k < 6; k++)
                    p6[k] = fmaf(rA[k][j], xj, p6[k]);
            }
            #pragma unroll
            for (int s = 8; s >= 1; s >>= 1)
                #pragma unroll
                for (int k = 0; k < 6; k++)
                    p6[k] += __shfl_xor_sync(0xffffffffu, p6[k], s, 16);
            if (lead) {
                #pragma unroll
                for (int k = 0; k < 6; k++) {
                    const int m  = ty + 32 * k;
                    const float zc = fmaf(ALPHA, p6[k], (1.0f - ALPHA) * sz[m]);
                    const float yv = sy[m];
                    const float v  = fmaf(yv, 1.0f / RHO, zc);
                    const float zn = fminf(fmaxf(v, sl[m]), su[m]);
                    const float yn = fmaf(RHO, zc - zn, yv);
                    sz[m] = zn;
                    sy[m] = yn;
                    sw[m] = fmaf(RHO, zn, -yn);
                }
            }
        }
        __syncthreads();
    }

    // ------------------------------------------------------------------
    // Output
    // ------------------------------------------------------------------
    for (int n = tid; n < Nn; n += NT)
        gout[(size_t)b * Nn + n] = sx[n];
}

extern "C" void kernel_launch(void* const* d_in, const int* in_sizes, int n_in,
                              void* d_out, int out_size)
{
    const float* P = (const float*)d_in[0];   // (256,128,128)
    const float* q = (const float*)d_in[1];   // (256,128)
    const float* A = (const float*)d_in[2];   // (256,192,128)
    const float* l = (const float*)d_in[3];   // (256,192)
    const float* u = (const float*)d_in[4];   // (256,192)
    float* out = (float*)d_out;               // (256,128)

    const int smem_bytes = SMEM_FLOATS * (int)sizeof(float);
    // Unconditional (no static guard). Not stream-ordered -> capture-legal; idempotent.
    cudaFuncSetAttribute(osqp_admm_kernel,
                         cudaFuncAttributeMaxDynamicSharedMemorySize,
                         smem_bytes);
    osqp_admm_kernel<<<Bb, NT, smem_bytes>>>(P, q, A, l, u, out);
}